// round 14
// baseline (speedup 1.0000x reference)
#include <cuda_runtime.h>
#include <cuda_fp16.h>
#include <cstdint>
#include <math.h>

#define BATCH  8
#define CINCH  256
#define HIDCH  256
#define NHEADS 8
#define HDIM   32
#define KSZ    31
#define PADW   15
#define WIDTH  16384

// ---- scratch (device globals; no allocation allowed) ----
__device__ float g_qWk[CINCH * NHEADS];
__device__ float g_qb[NHEADS];
__device__ float g_costE[BATCH * NHEADS * WIDTH];                 // 4 MB (L2-resident)
__device__ float g_rinv [BATCH * NHEADS * WIDTH];                 // 4 MB
__device__ __half g_vh[(size_t)BATCH * HIDCH * WIDTH];            // 64 MB (v, pre-cost)
__device__ __half g_xh[(size_t)BATCH * CINCH * WIDTH];            // 64 MB
__device__ __half g_rh[(size_t)BATCH * HIDCH * WIDTH];            // 64 MB
__device__ __half g_wvhi[HIDCH * CINCH];
__device__ __half g_wvlo[HIDCH * CINCH];
__device__ __half g_wohi[HIDCH * HIDCH];
__device__ __half g_wolo[HIDCH * HIDCH];

// ============================================================
// helpers
// ============================================================
__device__ __forceinline__ uint32_t smem_to_u32(const void* p) {
    uint32_t a;
    asm("{ .reg .u64 t; cvta.to.shared.u64 t, %1; cvt.u32.u64 %0, t; }" : "=r"(a) : "l"(p));
    return a;
}
__device__ __forceinline__ void ldsm_x4(uint32_t* r, uint32_t addr) {
    asm volatile("ldmatrix.sync.aligned.m8n8.x4.shared.b16 {%0,%1,%2,%3}, [%4];"
                 : "=r"(r[0]), "=r"(r[1]), "=r"(r[2]), "=r"(r[3]) : "r"(addr));
}
__device__ __forceinline__ void ldsm_x2t(uint32_t* r, uint32_t addr) {
    asm volatile("ldmatrix.sync.aligned.m8n8.x2.trans.shared.b16 {%0,%1}, [%2];"
                 : "=r"(r[0]), "=r"(r[1]) : "r"(addr));
}
__device__ __forceinline__ void mma_f16(float* d, const uint32_t* a, const uint32_t* b) {
    asm volatile("mma.sync.aligned.m16n8k16.row.col.f32.f16.f16.f32 "
                 "{%0,%1,%2,%3}, {%4,%5,%6,%7}, {%8,%9}, {%0,%1,%2,%3};"
                 : "+f"(d[0]), "+f"(d[1]), "+f"(d[2]), "+f"(d[3])
                 : "r"(a[0]), "r"(a[1]), "r"(a[2]), "r"(a[3]),
                   "r"(b[0]), "r"(b[1]));
}
__device__ __forceinline__ void split_f16(float v, __half& hi, __half& lo) {
    hi = __float2half_rn(v);
    lo = __float2half_rn(v - __half2float(hi));
}
__device__ __forceinline__ void cp_async16(uint32_t dst, const void* src) {
    asm volatile("cp.async.cg.shared.global [%0], [%1], 16;" :: "r"(dst), "l"(src));
}
#define CP_COMMIT() asm volatile("cp.async.commit_group;" ::: "memory")
#define CP_WAIT(n)  asm volatile("cp.async.wait_group %0;" :: "n"(n) : "memory")

// ============================================================
// Kernel 0: precompute qWk[D][h], qb[h]
// ============================================================
__global__ void precompute_kernel(const float* __restrict__ query,
                                  const float* __restrict__ Wk,
                                  const float* __restrict__ Wkb) {
    __shared__ float sq[CINCH];
    __shared__ float qn[CINCH];
    __shared__ float nrm[NHEADS];
    int tid = threadIdx.x;
    float qv = query[tid];
    sq[tid] = qv * qv;
    __syncthreads();
    if (tid < NHEADS) {
        float s = 0.f;
        #pragma unroll
        for (int d = 0; d < HDIM; d++) s += sq[tid * HDIM + d];
        nrm[tid] = sqrtf(s) + 1e-6f;
    }
    __syncthreads();
    qn[tid] = qv / nrm[tid / HDIM] * 0.17677669529663687f;
    __syncthreads();
    int D = tid;
    #pragma unroll
    for (int h = 0; h < NHEADS; h++) {
        float s = 0.f;
        const float* wrow = Wk + D * HIDCH + h * HDIM;
        #pragma unroll
        for (int d = 0; d < HDIM; d++) s += qn[h * HDIM + d] * wrow[d];
        g_qWk[D * NHEADS + h] = s;
    }
    if (tid < NHEADS) {
        float s = 0.f;
        #pragma unroll
        for (int d = 0; d < HDIM; d++) s += Wkb[tid * HDIM + d] * qn[tid * HDIM + d];
        g_qb[tid] = s;
    }
}

// ============================================================
// Weight split: W fp32 -> hi/lo fp16 planes (hi+lo exact to 2^-22)
// ============================================================
__global__ void wsplit_kernel(const float* __restrict__ W,
                              __half* __restrict__ hi,
                              __half* __restrict__ lo) {
    int base = (blockIdx.x * 256 + threadIdx.x) * 8;
    float4 v0 = *(const float4*)(W + base);
    float4 v1 = *(const float4*)(W + base + 4);
    float v[8] = {v0.x, v0.y, v0.z, v0.w, v1.x, v1.y, v1.z, v1.w};
    __half h[8], l[8];
    #pragma unroll
    for (int e = 0; e < 8; e++) split_f16(v[e], h[e], l[e]);
    *(uint4*)(hi + base) = *(uint4*)h;
    *(uint4*)(lo + base) = *(uint4*)l;
}

// ============================================================
// Fused: x -> fp16 plane AND cost_exp.
//   128 w-cols x 2 D-halves per block; smem reduce of head partials.
// ============================================================
__global__ void __launch_bounds__(256) xsplit_cost_kernel(const float* __restrict__ x) {
    __shared__ float sW[CINCH * NHEADS];
    __shared__ float sb[NHEADS];
    __shared__ float sred[NHEADS * 136];
    int tid = threadIdx.x;
    for (int i = tid; i < CINCH * NHEADS; i += 256) sW[i] = g_qWk[i];
    if (tid < NHEADS) sb[tid] = g_qb[tid];
    __syncthreads();

    const int tx = tid & 127;   // w column
    const int ty = tid >> 7;    // D half
    int b = blockIdx.y;
    int w = blockIdx.x * 128 + tx;
    const float* xb = x + (size_t)b * CINCH * WIDTH + w;
    __half* xh = g_xh + (size_t)b * CINCH * WIDTH + w;

    float acc[NHEADS];
    #pragma unroll
    for (int h = 0; h < NHEADS; h++) acc[h] = 0.f;

    const int D0 = ty * 128;
    #pragma unroll 8
    for (int d = 0; d < 128; d++) {
        int D = D0 + d;
        float v = __ldg(xb + (size_t)D * WIDTH);
        xh[(size_t)D * WIDTH] = __float2half_rn(v);
        #pragma unroll
        for (int h = 0; h < NHEADS; h++)
            acc[h] = fmaf(v, sW[D * NHEADS + h], acc[h]);
    }
    if (ty == 1) {
        #pragma unroll
        for (int h = 0; h < NHEADS; h++) sred[h * 136 + tx] = acc[h];
    }
    __syncthreads();
    if (ty == 0) {
        #pragma unroll
        for (int h = 0; h < NHEADS; h++) {
            float v = acc[h] + sred[h * 136 + tx] + sb[h];
            g_costE[((size_t)b * NHEADS + h) * WIDTH + w] = expf(v);
        }
    }
}

// ============================================================
// Kernel 2: denominator conv -> reciprocal
// ============================================================
__global__ void __launch_bounds__(256) denom_kernel(const float* __restrict__ rpe) {
    __shared__ float s[256 + 32];
    __shared__ float rks[KSZ];
    int h = blockIdx.y;
    int b = blockIdx.z;
    int w0 = blockIdx.x * 256;
    int tid = threadIdx.x;
    if (tid < KSZ) rks[tid] = expf(rpe[h * KSZ + tid]);
    const float* crow = g_costE + ((size_t)b * NHEADS + h) * WIDTH;
    #pragma unroll
    for (int i = tid; i < 256 + 32; i += 256) {
        int g = w0 - PADW + i;
        s[i] = (g >= 0 && g < WIDTH) ? crow[g] : 0.f;
    }
    __syncthreads();
    float rkr[KSZ];
    #pragma unroll
    for (int k = 0; k < KSZ; k++) rkr[k] = rks[k];
    float sc = 0.f;
    #pragma unroll
    for (int k = 0; k < KSZ; k++) sc = fmaf(s[tid + k], rkr[k], sc);
    g_rinv[((size_t)b * NHEADS + h) * WIDTH + w0 + tid] = 1.0f / sc;
}

// ============================================================
// Kernel 3: conv on p = cE * v, * rinv -> g_rh
//   Tile s[j] = p[w0-16+j]  (pair-aligned vectorized fill)
//   Output w=w0+t8+o uses tap k at s[t8 + m'], k = m' - o - 1.
// ============================================================
#define CTILE 2048
#define CPAIRS 1040    // (2048+32)/2 halves
__global__ void __launch_bounds__(256) conv_kernel(const float* __restrict__ rpe) {
    __shared__ __align__(16) float s[2 * CPAIRS + 8];
    __shared__ float rks[KSZ];
    int c = blockIdx.y;
    int h = c >> 5;
    int b = blockIdx.z;
    int w0 = blockIdx.x * CTILE;
    int tid = threadIdx.x;
    if (tid < KSZ) rks[tid] = expf(rpe[h * KSZ + tid]);

    const __half* vrow = g_vh + ((size_t)b * HIDCH + c) * WIDTH;
    const float* crow = g_costE + ((size_t)b * NHEADS + h) * WIDTH;
    for (int m = tid; m < CPAIRS; m += 256) {
        int g = w0 - 16 + 2 * m;
        float2 pv;
        if (g >= 0 && g + 1 < WIDTH) {
            __half2 v2 = *(const __half2*)(vrow + g);
            float2 c2 = *(const float2*)(crow + g);
            pv.x = __half2float(__low2half(v2))  * c2.x;
            pv.y = __half2float(__high2half(v2)) * c2.y;
        } else {
            pv.x = (g >= 0 && g < WIDTH)
                 ? __half2float(__ldg(vrow + g)) * __ldg(crow + g) : 0.f;
            pv.y = (g + 1 >= 0 && g + 1 < WIDTH)
                 ? __half2float(__ldg(vrow + g + 1)) * __ldg(crow + g + 1) : 0.f;
        }
        *(float2*)&s[2 * m] = pv;
    }
    __syncthreads();

    float rkr[KSZ];
    #pragma unroll
    for (int k = 0; k < KSZ; k++) rkr[k] = rks[k];

    const int t8 = tid * 8;
    float a[8];
    #pragma unroll
    for (int o = 0; o < 8; o++) a[o] = 0.f;

    #pragma unroll
    for (int u = 0; u < 10; u++) {
        float4 v4 = *(const float4*)&s[t8 + u * 4];
        float vv[4] = {v4.x, v4.y, v4.z, v4.w};
        #pragma unroll
        for (int e = 0; e < 4; e++) {
            const int m = u * 4 + e;
            #pragma unroll
            for (int o = 0; o < 8; o++) {
                const int k = m - o - 1;
                if (k >= 0 && k < KSZ) a[o] = fmaf(vv[e], rkr[k], a[o]);
            }
        }
    }
    const float* rinv = g_rinv + ((size_t)b * NHEADS + h) * WIDTH + w0 + t8;
    float4 r0 = *(const float4*)rinv;
    float4 r1 = *(const float4*)(rinv + 4);
    __half o16[8];
    o16[0] = __float2half_rn(a[0] * r0.x);
    o16[1] = __float2half_rn(a[1] * r0.y);
    o16[2] = __float2half_rn(a[2] * r0.z);
    o16[3] = __float2half_rn(a[3] * r0.w);
    o16[4] = __float2half_rn(a[4] * r1.x);
    o16[5] = __float2half_rn(a[5] * r1.y);
    o16[6] = __float2half_rn(a[6] * r1.z);
    o16[7] = __float2half_rn(a[7] * r1.w);
    size_t obase = ((size_t)b * HIDCH + c) * WIDTH + w0 + t8;
    *(uint4*)(g_rh + obase) = *(uint4*)o16;
}

// ============================================================
// HMMA fp16 2-term GEMM, 3-stage cp.async pipeline
//   MODE 0: C = x@Wv + bv  -> fp16 g_vh
//   MODE 1: C = r@Wo + bo  -> fp32 Out
// ============================================================
#define SA_STRIDE 80     // bytes per A row (32 fp16 + 16B pad)
#define SB_STRIDE 272    // bytes per B k-row (128 fp16 + 16B pad)
#define OFF_AHI 0
#define OFF_ALO 10240
#define OFF_B   20480
#define STG_SZ  29184    // 20480 + 32*272
#define SM_STG  1024
#define SM_TOT_MMA (SM_STG + 3 * STG_SZ)   // 88576

template <int MODE>
__global__ void __launch_bounds__(256, 2)
gemm_mma(const float* __restrict__ bias, float* __restrict__ Out) {
    extern __shared__ __align__(16) char smem[];
    const uint32_t sbu = smem_to_u32(smem);
    float* sbias = (float*)smem;

    const int tid  = threadIdx.x;
    const int wid  = tid >> 5;
    const int lane = tid & 31;
    const int warp_m = wid >> 2;
    const int warp_n = wid & 3;
    const int bn = blockIdx.x * 128;   // w base
    const int cm = blockIdx.y * 128;   // c base
    const int b  = blockIdx.z;

    const __half* Whi = (MODE == 0) ? g_wvhi : g_wohi;
    const __half* Wlo = (MODE == 0) ? g_wvlo : g_wolo;
    const __half* Xh  = ((MODE == 0) ? g_xh : g_rh) + (size_t)b * CINCH * WIDTH;

    if (tid < 128) sbias[tid] = bias[cm + tid];

    const int av0 = tid * 2;
    auto issue = [&](int chunk, int slot) {
        const uint32_t stgu = sbu + SM_STG + slot * STG_SZ;
        const int k0 = chunk * 32;
        #pragma unroll
        for (int j = 0; j < 2; j++) {
            int v = av0 + j;
            int r = v >> 2, c4 = v & 3;
            const __half* sh = Whi + (size_t)(cm + r) * CINCH + k0 + c4 * 8;
            const __half* sl = Wlo + (size_t)(cm + r) * CINCH + k0 + c4 * 8;
            cp_async16(stgu + OFF_AHI + r * SA_STRIDE + c4 * 16, sh);
            cp_async16(stgu + OFF_ALO + r * SA_STRIDE + c4 * 16, sl);
        }
        #pragma unroll
        for (int j = 0; j < 2; j++) {
            int v = av0 + j;
            int r = v >> 4, c = v & 15;
            const __half* sx = Xh + (size_t)(k0 + r) * WIDTH + bn + c * 8;
            cp_async16(stgu + OFF_B + r * SB_STRIDE + c * 16, sx);
        }
        CP_COMMIT();
    };

    float d[4][4][4];
    #pragma unroll
    for (int mi = 0; mi < 4; mi++)
        #pragma unroll
        for (int ni = 0; ni < 4; ni++)
            #pragma unroll
            for (int e = 0; e < 4; e++) d[mi][ni][e] = 0.f;

    issue(0, 0);
    issue(1, 1);

    for (int i = 0; i < 8; i++) {
        CP_WAIT(1);
        __syncthreads();
        if (i < 6) issue(i + 2, (i + 2) % 3);

        const uint32_t stgb = sbu + SM_STG + (i % 3) * STG_SZ;
        #pragma unroll
        for (int ks = 0; ks < 2; ks++) {
            uint32_t ah[4][4], al[4][4];
            #pragma unroll
            for (int mi = 0; mi < 4; mi++) {
                uint32_t addr = stgb + OFF_AHI
                    + (uint32_t)(warp_m * 64 + mi * 16 + (lane & 15)) * SA_STRIDE
                    + ks * 32 + (lane >> 4) * 16;
                ldsm_x4(ah[mi], addr);
                ldsm_x4(al[mi], addr + (OFF_ALO - OFF_AHI));
            }
            #pragma unroll
            for (int ni = 0; ni < 4; ni++) {
                uint32_t addr = stgb + OFF_B
                    + (uint32_t)(ks * 16 + (lane & 15)) * SB_STRIDE
                    + (warp_n * 32 + ni * 8) * 2;
                uint32_t bh[2];
                ldsm_x2t(bh, addr);
                #pragma unroll
                for (int mi = 0; mi < 4; mi++) mma_f16(d[mi][ni], ah[mi], bh);
                #pragma unroll
                for (int mi = 0; mi < 4; mi++) mma_f16(d[mi][ni], al[mi], bh);
            }
        }
    }

    // ---- epilogue ----
    #pragma unroll
    for (int mi = 0; mi < 4; mi++) {
        int cl0 = warp_m * 64 + mi * 16 + (lane >> 2);
        int c0 = cm + cl0;
        float bv0 = sbias[cl0];
        float bv1 = sbias[cl0 + 8];
        #pragma unroll
        for (int ni = 0; ni < 4; ni++) {
            int w0 = bn + warp_n * 32 + ni * 8 + (lane & 3) * 2;
            if (MODE == 0) {
                __half2 p0, p1;
                p0.x = __float2half_rn(d[mi][ni][0] + bv0);
                p0.y = __float2half_rn(d[mi][ni][1] + bv0);
                p1.x = __float2half_rn(d[mi][ni][2] + bv1);
                p1.y = __float2half_rn(d[mi][ni][3] + bv1);
                *(__half2*)&g_vh[((size_t)b * HIDCH + c0) * WIDTH + w0]     = p0;
                *(__half2*)&g_vh[((size_t)b * HIDCH + c0 + 8) * WIDTH + w0] = p1;
            } else {
                float2 o0, o1;
                o0.x = d[mi][ni][0] + bv0;
                o0.y = d[mi][ni][1] + bv0;
                o1.x = d[mi][ni][2] + bv1;
                o1.y = d[mi][ni][3] + bv1;
                *(float2*)&Out[((size_t)b * HIDCH + c0) * WIDTH + w0]     = o0;
                *(float2*)&Out[((size_t)b * HIDCH + c0 + 8) * WIDTH + w0] = o1;
            }
        }
    }
}

// ============================================================
extern "C" void kernel_launch(void* const* d_in, const int* in_sizes, int n_in,
                              void* d_out, int out_size) {
    const float* x     = (const float*)d_in[0];
    const float* query = (const float*)d_in[1];
    const float* Wk    = (const float*)d_in[2];
    const float* Wkb   = (const float*)d_in[3];
    const float* rpe   = (const float*)d_in[4];
    const float* Wv    = (const float*)d_in[5];
    const float* bv    = (const float*)d_in[6];
    const float* Wo    = (const float*)d_in[7];
    const float* bo    = (const float*)d_in[8];
    float* out = (float*)d_out;

    cudaFuncSetAttribute(gemm_mma<0>, cudaFuncAttributeMaxDynamicSharedMemorySize, SM_TOT_MMA);
    cudaFuncSetAttribute(gemm_mma<1>, cudaFuncAttributeMaxDynamicSharedMemorySize, SM_TOT_MMA);

    __half *dvh, *dvl, *doh, *dol;
    cudaGetSymbolAddress((void**)&dvh, g_wvhi);
    cudaGetSymbolAddress((void**)&dvl, g_wvlo);
    cudaGetSymbolAddress((void**)&doh, g_wohi);
    cudaGetSymbolAddress((void**)&dol, g_wolo);

    // launch order chosen so gemm_mma<0> is the 4th launch (ncu visibility)
    precompute_kernel<<<1, 256>>>(query, Wk, Wkb);                                    // 1
    xsplit_cost_kernel<<<dim3(WIDTH / 128, BATCH), 256>>>(x);                         // 2
    wsplit_kernel<<<32, 256>>>(Wv, dvh, dvl);                                         // 3
    gemm_mma<0><<<dim3(WIDTH / 128, HIDCH / 128, BATCH), 256, SM_TOT_MMA>>>(bv, nullptr); // 4
    wsplit_kernel<<<32, 256>>>(Wo, doh, dol);                                         // 5
    denom_kernel<<<dim3(WIDTH / 256, NHEADS, BATCH), 256>>>(rpe);                     // 6
    conv_kernel<<<dim3(WIDTH / CTILE, HIDCH, BATCH), 256>>>(rpe);                     // 7
    gemm_mma<1><<<dim3(WIDTH / 128, HIDCH / 128, BATCH), 256, SM_TOT_MMA>>>(bo, out); // 8
}